// round 10
// baseline (speedup 1.0000x reference)
#include <cuda_runtime.h>
#include <cuda_fp16.h>
#include <cstdint>

// ------------------------- problem constants -------------------------
#define CC 256
#define LL 8192
#define BB 32
#define TL 64            // positions per CTA
#define SC 64            // K superchunk
#define NSUPER 4

// ------------------------- smem layout (bytes) -----------------------
#define XOFF(s)  ((s) * 8192)       // x fp16: 64 k-rows x 128B (xor-swizzled), 2 slots
#define SBIAS    16384              // 256 floats
#define SQBUF    17408              // 4 x 64 floats
#define SCALE    18432              // 64 floats
#define SMEM_BYTES 18688

// ------------------------- device scratch ----------------------------
// W' fp16 pairs in exact A-fragment order (per 32-k chunk):
// idx = (((kc*2+ks)*16 + mb)*32 + lane)*4 + reg   (each u32 = 2 fp16, k-pair)
// Read directly by MMA warps via LDG.128 (L1-resident: 128KB total).
__device__ __align__(16) unsigned g_Wf[CC * CC / 2];
__device__ float g_bias[CC];

// ------------------------- helpers -----------------------------------
__device__ __forceinline__ uint32_t smem_u32(const void* p) {
    uint32_t a;
    asm("{ .reg .u64 t; cvta.to.shared.u64 t, %1; cvt.u32.u64 %0, t; }"
        : "=r"(a) : "l"(p));
    return a;
}
__device__ __forceinline__ uint32_t pkh2(float a, float b) {
    __half2 h = __floats2half2_rn(a, b);
    return *reinterpret_cast<uint32_t*>(&h);
}
__device__ __forceinline__ void ldsm_x2t(uint32_t* r, uint32_t addr) {
    asm volatile("ldmatrix.sync.aligned.m8n8.x2.trans.shared.b16 {%0,%1}, [%2];"
                 : "=r"(r[0]), "=r"(r[1]) : "r"(addr));
}
__device__ __forceinline__ void mma_f16(float* d, const uint32_t* a, const uint32_t* b) {
    asm volatile(
        "mma.sync.aligned.m16n8k16.row.col.f32.f16.f16.f32 "
        "{%0,%1,%2,%3}, {%4,%5,%6,%7}, {%8,%9}, {%0,%1,%2,%3};"
        : "+f"(d[0]), "+f"(d[1]), "+f"(d[2]), "+f"(d[3])
        : "r"(a[0]), "r"(a[1]), "r"(a[2]), "r"(a[3]), "r"(b[0]), "r"(b[1]));
}
#define BAR_GROUP(id) asm volatile("bar.sync %0, 128;" :: "r"(id) : "memory")

// ------------------------- prep kernel -------------------------------
__global__ void fold_kernel(const float* __restrict__ W, const float* __restrict__ b,
                            const float* __restrict__ gamma, const float* __restrict__ beta,
                            const float* __restrict__ mean, const float* __restrict__ var) {
    int o = blockIdx.x;
    int j = threadIdx.x;          // c pair: c = 2j, 2j+1
    float inv = gamma[o] * rsqrtf(var[o] + 1e-5f);
    int c = 2 * j;
    float w0 = W[o * CC + c] * inv;
    float w1 = W[o * CC + c + 1] * inv;
    int kc = c >> 5;              // 32-chunk
    int ks = (c >> 4) & 1;        // k16 step within chunk
    int kl = c & 15;              // k within 16 (even)
    int mb = o >> 4;
    int lane = (o & 7) * 4 + ((kl >> 1) & 3);
    int reg  = ((o >> 3) & 1) + 2 * (kl >> 3);
    g_Wf[(((kc * 2 + ks) * 16 + mb) * 32 + lane) * 4 + reg] = pkh2(w0, w1);
    if (j == 0) g_bias[o] = b[o] * inv + beta[o] - mean[o] * inv;
}

// ------------------------- main kernel -------------------------------
// 256 threads, 8 warps: wm 0..3 (64 oc), wn 0..1 (32 pos). 2 CTAs/SM.
// Tile 256 oc x 64 pos; K in 4 superchunks of 64. Each wn-group (128 thr)
// stages + consumes ITS OWN position half; sync = group-local bar.sync only.
// W fragments straight from gmem (L1-resident).
extern "C" __global__ void __launch_bounds__(256, 2)
caps_kernel(const float* __restrict__ x, float* __restrict__ out) {
    extern __shared__ char smem[];
    const uint32_t sbu = smem_u32(smem);
    const int t    = threadIdx.x;
    const int lane = t & 31;
    const int wid  = t >> 5;
    const int wm   = wid & 3;
    const int wn   = wid >> 2;          // group id (threads g*128..g*128+127)
    const int m0   = wm * 64;
    const int bb   = blockIdx.y;
    const int l0   = blockIdx.x * TL;

    ((float*)(smem + SBIAS))[t] = g_bias[t];

    const float* xg = x + (size_t)bb * CC * LL + l0;

    float acc[4][4][4];
    #pragma unroll
    for (int i = 0; i < 4; i++)
        #pragma unroll
        for (int j = 0; j < 4; j++)
            #pragma unroll
            for (int q = 0; q < 4; q++) acc[i][j][q] = 0.0f;

    // ---- group-owned x staging -------------------------------------
    // Group g owns logical segs S = g*4 + s4 (positions g*32 .. g*32+31).
    // Unit v (0..255) = (row r = v>>2, s4 = v&3); pass p covers v = u + 128p,
    // where u = t & 127. Physical seg = S ^ (r & 7)  (same map as before,
    // so ldmatrix addressing is unchanged).
    const int u   = t & 127;
    float4 xa, xb2;
    auto ldg_x = [&](int sc, int p) {
        int v = u + 128 * p;
        int r = v >> 2, s4 = v & 3;
        const float* s = xg + (size_t)(sc * SC + r) * LL + (wn * 4 + s4) * 8;
        xa  = __ldg((const float4*)s);
        xb2 = __ldg((const float4*)(s + 4));
    };
    auto stage_x = [&](int st, int p) {
        int v = u + 128 * p;
        int r = v >> 2, s4 = v & 3;
        uint32_t off = (uint32_t)(r * 128 + (((wn * 4 + s4) ^ (r & 7)) << 4));
        uint4 w;
        w.x = pkh2(xa.x, xa.y);   w.y = pkh2(xa.z, xa.w);
        w.z = pkh2(xb2.x, xb2.y); w.w = pkh2(xb2.z, xb2.w);
        *(uint4*)(smem + XOFF(st) + off) = w;
    };

    // ---- one k16-step of mma (A frags via LDG.128, L1-hit) ----------
    const uint4* Wg0 = (const uint4*)g_Wf;      // 1024 uint4 per 32-chunk
    auto mma_ks = [&](int st, int sc, int ks) {
        int c32  = sc * 2 + (ks >> 1);
        int ks16 = ks & 1;
        const uint4* Wg = Wg0 + (size_t)c32 * 1024 + wm * 128 + lane;
        const uint32_t Xb = sbu + XOFF(st);
        uint32_t af[4][4], bf[4][2];
        #pragma unroll
        for (int i = 0; i < 4; i++) {
            uint4 v = __ldg(Wg + (ks16 * 16 + i) * 32);
            af[i][0] = v.x; af[i][1] = v.y; af[i][2] = v.z; af[i][3] = v.w;
        }
        #pragma unroll
        for (int j = 0; j < 4; j++)
            ldsm_x2t(bf[j], Xb + (uint32_t)((ks * 16 + (lane & 15)) * 128
                               + (((wn * 4 + j) ^ (lane & 7)) << 4)));
        #pragma unroll
        for (int i = 0; i < 4; i++)
            #pragma unroll
            for (int j = 0; j < 4; j++)
                mma_f16(acc[i][j], af[i], bf[j]);
    };

    // ---- pipeline: 2-slot ring, group-local sync only ---------------
    ldg_x(0, 0); stage_x(0, 0);
    ldg_x(0, 1); stage_x(0, 1);

    for (int s = 0; s < NSUPER; s++) {
        const int st = s & 1;
        BAR_GROUP(wn + 1);                 // group g: stage(s) visible
        if (s + 1 < NSUPER) ldg_x(s + 1, 0);
        mma_ks(st, s, 0);
        mma_ks(st, s, 1);
        if (s + 1 < NSUPER) {
            stage_x(st ^ 1, 0);            // slot (s+1)&1 != st: safe
            ldg_x(s + 1, 1);
        }
        mma_ks(st, s, 2);
        mma_ks(st, s, 3);
        if (s + 1 < NSUPER) stage_x(st ^ 1, 1);
    }

    // ---- epilogue: bias + squash + direct store ----------------------
    const float* sbias = (const float*)(smem + SBIAS);
    const int gid = lane >> 2;     // row-within-16 group
    const int qid = lane & 3;      // position pair
    const int n0  = wn * 32;

    float sqA[4], sqB[4];
    #pragma unroll
    for (int j = 0; j < 4; j++) { sqA[j] = 0.0f; sqB[j] = 0.0f; }

    #pragma unroll
    for (int i = 0; i < 4; i++) {
        int r0 = m0 + i * 16 + gid;
        float b0 = sbias[r0], b1 = sbias[r0 + 8];
        #pragma unroll
        for (int j = 0; j < 4; j++) {
            float y0 = acc[i][j][0] + b0;
            float y1 = acc[i][j][1] + b0;
            float y2 = acc[i][j][2] + b1;
            float y3 = acc[i][j][3] + b1;
            acc[i][j][0] = y0; acc[i][j][1] = y1;
            acc[i][j][2] = y2; acc[i][j][3] = y3;
            sqA[j] += y0 * y0 + y2 * y2;
            sqB[j] += y1 * y1 + y3 * y3;
        }
    }
    #pragma unroll
    for (int j = 0; j < 4; j++) {
        #pragma unroll
        for (int m = 4; m < 32; m <<= 1) {
            sqA[j] += __shfl_xor_sync(0xffffffffu, sqA[j], m);
            sqB[j] += __shfl_xor_sync(0xffffffffu, sqB[j], m);
        }
    }
    float* sqb = (float*)(smem + SQBUF);
    if (lane < 4) {
        #pragma unroll
        for (int j = 0; j < 4; j++) {
            int col = n0 + j * 8 + lane * 2;
            sqb[wm * 64 + col]     = sqA[j];
            sqb[wm * 64 + col + 1] = sqB[j];
        }
    }
    __syncthreads();
    if (t < 64) {
        float s = sqb[t] + sqb[64 + t] + sqb[128 + t] + sqb[192 + t];
        float n = sqrtf(s);
        ((float*)(smem + SCALE))[t] = s / ((1.0f + s) * (n + 1e-8f));
    }
    __syncthreads();

    const float* scl = (const float*)(smem + SCALE);
    float* og = out + ((size_t)bb * LL + l0) * CC;
    #pragma unroll
    for (int j = 0; j < 4; j++) {
        int c0 = n0 + j * 8 + qid * 2;       // position
        float s0 = scl[c0], s1 = scl[c0 + 1];
        float* p0 = og + (size_t)c0 * CC;
        float* p1 = og + (size_t)(c0 + 1) * CC;
        #pragma unroll
        for (int i = 0; i < 4; i++) {
            int r0 = m0 + i * 16 + gid;      // channel
            p0[r0]     = acc[i][j][0] * s0;
            p1[r0]     = acc[i][j][1] * s1;
            p0[r0 + 8] = acc[i][j][2] * s0;
            p1[r0 + 8] = acc[i][j][3] * s1;
        }
    }
}

// ------------------------- launch ------------------------------------
extern "C" void kernel_launch(void* const* d_in, const int* in_sizes, int n_in,
                              void* d_out, int out_size) {
    const float* x     = (const float*)d_in[0];
    const float* W     = (const float*)d_in[1];
    const float* b     = (const float*)d_in[2];
    const float* gamma = (const float*)d_in[3];
    const float* beta  = (const float*)d_in[4];
    const float* mean  = (const float*)d_in[5];
    const float* var   = (const float*)d_in[6];
    float* out = (float*)d_out;

    fold_kernel<<<CC, 128>>>(W, b, gamma, beta, mean, var);

    cudaFuncSetAttribute(caps_kernel,
                         cudaFuncAttributeMaxDynamicSharedMemorySize, SMEM_BYTES);
    dim3 grid(LL / TL, BB);
    caps_kernel<<<grid, 256, SMEM_BYTES>>>(x, out);
}

// round 11
// speedup vs baseline: 1.1491x; 1.1491x over previous
#include <cuda_runtime.h>
#include <cuda_fp16.h>
#include <cstdint>

// ------------------------- problem constants -------------------------
#define CC 256
#define LL 8192
#define BB 32
#define TL 32            // positions per CTA
#define KC 32            // K chunk
#define NCHUNK 8
#define NSTAGE 3

// ------------------------- smem layout (bytes) -----------------------
#define XOFF(s)  ((s) * 2048)       // x fp16: 32 k-rows x 64B (swizzled)
#define SBIAS    6144               // 256 floats
#define SQBUF    7168               // 4 x 32 floats
#define SCALE    7680               // 32 floats
#define SMEM_BYTES 7808

// ------------------------- device scratch ----------------------------
// W' fp16 pairs in exact A-fragment order (per 32-k chunk):
// idx = (((kc*2+ks)*16 + mb)*32 + lane)*4 + reg   (each u32 = 2 fp16, k-pair)
__device__ __align__(16) unsigned g_Wf[CC * CC / 2];
__device__ float g_bias[CC];

// ------------------------- helpers -----------------------------------
__device__ __forceinline__ uint32_t smem_u32(const void* p) {
    uint32_t a;
    asm("{ .reg .u64 t; cvta.to.shared.u64 t, %1; cvt.u32.u64 %0, t; }"
        : "=r"(a) : "l"(p));
    return a;
}
__device__ __forceinline__ uint32_t pkh2(float a, float b) {
    __half2 h = __floats2half2_rn(a, b);
    return *reinterpret_cast<uint32_t*>(&h);
}
__device__ __forceinline__ void ldsm_x2t(uint32_t* r, uint32_t addr) {
    asm volatile("ldmatrix.sync.aligned.m8n8.x2.trans.shared.b16 {%0,%1}, [%2];"
                 : "=r"(r[0]), "=r"(r[1]) : "r"(addr));
}
__device__ __forceinline__ void mma_f16(float* d, const uint32_t* a, const uint32_t* b) {
    asm volatile(
        "mma.sync.aligned.m16n8k16.row.col.f32.f16.f16.f32 "
        "{%0,%1,%2,%3}, {%4,%5,%6,%7}, {%8,%9}, {%0,%1,%2,%3};"
        : "+f"(d[0]), "+f"(d[1]), "+f"(d[2]), "+f"(d[3])
        : "r"(a[0]), "r"(a[1]), "r"(a[2]), "r"(a[3]), "r"(b[0]), "r"(b[1]));
}

// ------------------------- prep kernel -------------------------------
__global__ void fold_kernel(const float* __restrict__ W, const float* __restrict__ b,
                            const float* __restrict__ gamma, const float* __restrict__ beta,
                            const float* __restrict__ mean, const float* __restrict__ var) {
    int o = blockIdx.x;
    int j = threadIdx.x;          // c pair: c = 2j, 2j+1
    float inv = gamma[o] * rsqrtf(var[o] + 1e-5f);
    int c = 2 * j;
    float w0 = W[o * CC + c] * inv;
    float w1 = W[o * CC + c + 1] * inv;
    int kc = c >> 5;
    int ks = (c >> 4) & 1;
    int kl = c & 15;
    int mb = o >> 4;
    int lane = (o & 7) * 4 + ((kl >> 1) & 3);
    int reg  = ((o >> 3) & 1) + 2 * (kl >> 3);
    g_Wf[(((kc * 2 + ks) * 16 + mb) * 32 + lane) * 4 + reg] = pkh2(w0, w1);
    if (j == 0) g_bias[o] = b[o] * inv + beta[o] - mean[o] * inv;
}

// ------------------------- main kernel -------------------------------
// 128 threads, 4 warps (each owns 64 oc x full 32 pos). 3 CTAs/SM.
// Tile 256 oc x 32 pos; K in 8 chunks of 32. W frags: direct LDG (L1-hot).
// x: LDG->pkh2->STS 3-ring. Explicit fragment double-buffering across ks.
extern "C" __global__ void __launch_bounds__(128, 3)
caps_kernel(const float* __restrict__ x, float* __restrict__ out) {
    extern __shared__ char smem[];
    const uint32_t sbu = smem_u32(smem);
    const int t    = threadIdx.x;
    const int lane = t & 31;
    const int wm   = t >> 5;            // warp = m-slice
    const int m0   = wm * 64;
    const int bb   = blockIdx.y;
    const int l0   = blockIdx.x * TL;

    ((float*)(smem + SBIAS))[t]       = g_bias[t];
    ((float*)(smem + SBIAS))[t + 128] = g_bias[t + 128];

    const float* xg = x + (size_t)bb * CC * LL + l0;

    float acc[4][4][4];
    #pragma unroll
    for (int i = 0; i < 4; i++)
        #pragma unroll
        for (int j = 0; j < 4; j++)
            #pragma unroll
            for (int q = 0; q < 4; q++) acc[i][j][q] = 0.0f;

    // ---- x staging: thread t -> row r = t>>2 (k), seg p8 = t&3 (8 pos) --
    // swizzle: phys seg = p8 ^ ((r>>1)&3); rows are 64B.
    const int xr = t >> 2;
    const int p8 = t & 3;
    const uint32_t xsts = (uint32_t)(xr * 64 + ((p8 ^ ((xr >> 1) & 3)) << 4));
    float4 xa, xb2;
    auto ldg_x = [&](int kc) {
        const float* s = xg + (size_t)(kc * KC + xr) * LL + p8 * 8;
        xa  = __ldg((const float4*)s);
        xb2 = __ldg((const float4*)(s + 4));
    };
    auto stage_x = [&](int st) {
        uint4 u;
        u.x = pkh2(xa.x, xa.y);   u.y = pkh2(xa.z, xa.w);
        u.z = pkh2(xb2.x, xb2.y); u.w = pkh2(xb2.z, xb2.w);
        *(uint4*)(smem + XOFF(st) + xsts) = u;
    };

    // ---- fragment loads ----------------------------------------------
    const uint4* Wg0 = (const uint4*)g_Wf;       // 1024 uint4 per 32-chunk
    auto load_af = [&](uint32_t (*af)[4], int kc, int ks16) {
        const uint4* Wg = Wg0 + (size_t)(kc * 2 + ks16) * 512 + wm * 128 + lane;
        #pragma unroll
        for (int i = 0; i < 4; i++) {
            uint4 v = __ldg(Wg + i * 32);
            af[i][0] = v.x; af[i][1] = v.y; af[i][2] = v.z; af[i][3] = v.w;
        }
    };
    auto load_bf = [&](uint32_t (*bf)[2], int st, int ks16) {
        const uint32_t Xb = sbu + XOFF(st);
        int row = ks16 * 16 + (lane & 15);
        #pragma unroll
        for (int j = 0; j < 4; j++)
            ldsm_x2t(bf[j], Xb + (uint32_t)(row * 64
                               + ((j ^ ((row >> 1) & 3)) << 4)));
    };
    auto mma16 = [&](uint32_t (*af)[4], uint32_t (*bf)[2]) {
        #pragma unroll
        for (int i = 0; i < 4; i++)
            #pragma unroll
            for (int j = 0; j < 4; j++)
                mma_f16(acc[i][j], af[i], bf[j]);
    };

    // ---- pipeline: 3-ring, 1 barrier/chunk, frag double-buffer -------
    ldg_x(0); stage_x(0);
    ldg_x(1); stage_x(1);

    uint32_t af0[4][4], af1[4][4], bf0[4][2], bf1[4][2];
    for (int k = 0; k < NCHUNK; k++) {
        const int st = k % NSTAGE;
        if (k + 2 < NCHUNK) ldg_x(k + 2);
        __syncthreads();                   // stage(k) visible (4 warps: cheap)
        load_bf(bf0, st, 0);
        load_af(af0, k, 0);
        load_bf(bf1, st, 1);               // prefetch ks1 before ks0 MMA
        load_af(af1, k, 1);
        mma16(af0, bf0);
        if (k + 2 < NCHUNK) stage_x((k + 2) % NSTAGE);
        mma16(af1, bf1);
    }

    // ---- epilogue: bias + squash + store ------------------------------
    const float* sbias = (const float*)(smem + SBIAS);
    const int gid = lane >> 2;
    const int qid = lane & 3;

    float sqA[4], sqB[4];
    #pragma unroll
    for (int j = 0; j < 4; j++) { sqA[j] = 0.0f; sqB[j] = 0.0f; }

    #pragma unroll
    for (int i = 0; i < 4; i++) {
        int r0 = m0 + i * 16 + gid;
        float b0 = sbias[r0], b1 = sbias[r0 + 8];
        #pragma unroll
        for (int j = 0; j < 4; j++) {
            float y0 = acc[i][j][0] + b0;
            float y1 = acc[i][j][1] + b0;
            float y2 = acc[i][j][2] + b1;
            float y3 = acc[i][j][3] + b1;
            acc[i][j][0] = y0; acc[i][j][1] = y1;
            acc[i][j][2] = y2; acc[i][j][3] = y3;
            sqA[j] += y0 * y0 + y2 * y2;
            sqB[j] += y1 * y1 + y3 * y3;
        }
    }
    #pragma unroll
    for (int j = 0; j < 4; j++) {
        #pragma unroll
        for (int m = 4; m < 32; m <<= 1) {
            sqA[j] += __shfl_xor_sync(0xffffffffu, sqA[j], m);
            sqB[j] += __shfl_xor_sync(0xffffffffu, sqB[j], m);
        }
    }
    float* sqb = (float*)(smem + SQBUF);
    if (lane < 4) {
        #pragma unroll
        for (int j = 0; j < 4; j++) {
            int col = j * 8 + lane * 2;
            sqb[wm * 32 + col]     = sqA[j];
            sqb[wm * 32 + col + 1] = sqB[j];
        }
    }
    __syncthreads();
    if (t < 32) {
        float s = sqb[t] + sqb[32 + t] + sqb[64 + t] + sqb[96 + t];
        float n = sqrtf(s);
        ((float*)(smem + SCALE))[t] = s / ((1.0f + s) * (n + 1e-8f));
    }
    __syncthreads();

    const float* scl = (const float*)(smem + SCALE);
    float* og = out + ((size_t)bb * LL + l0) * CC;
    #pragma unroll
    for (int j = 0; j < 4; j++) {
        int c0 = j * 8 + qid * 2;            // position
        float s0 = scl[c0], s1 = scl[c0 + 1];
        float* p0 = og + (size_t)c0 * CC;
        float* p1 = og + (size_t)(c0 + 1) * CC;
        #pragma unroll
        for (int i = 0; i < 4; i++) {
            int r0 = m0 + i * 16 + gid;      // channel
            p0[r0]     = acc[i][j][0] * s0;
            p1[r0]     = acc[i][j][1] * s1;
            p0[r0 + 8] = acc[i][j][2] * s0;
            p1[r0 + 8] = acc[i][j][3] * s1;
        }
    }
}

// ------------------------- launch ------------------------------------
extern "C" void kernel_launch(void* const* d_in, const int* in_sizes, int n_in,
                              void* d_out, int out_size) {
    const float* x     = (const float*)d_in[0];
    const float* W     = (const float*)d_in[1];
    const float* b     = (const float*)d_in[2];
    const float* gamma = (const float*)d_in[3];
    const float* beta  = (const float*)d_in[4];
    const float* mean  = (const float*)d_in[5];
    const float* var   = (const float*)d_in[6];
    float* out = (float*)d_out;

    fold_kernel<<<CC, 128>>>(W, b, gamma, beta, mean, var);

    cudaFuncSetAttribute(caps_kernel,
                         cudaFuncAttributeMaxDynamicSharedMemorySize, SMEM_BYTES);
    dim3 grid(LL / TL, BB);
    caps_kernel<<<grid, 128, SMEM_BYTES>>>(x, out);
}

// round 12
// speedup vs baseline: 1.1884x; 1.0342x over previous
#include <cuda_runtime.h>
#include <cuda_fp16.h>
#include <cstdint>

// ------------------------- problem constants -------------------------
#define CC 256
#define LL 8192
#define BB 32
#define TL 32            // positions per CTA
#define KC 32            // K chunk
#define NCHUNK 8
#define NSTAGE 4

// ------------------------- smem layout (bytes) -----------------------
#define XOFF(s)  ((s) * 2048)       // x fp16: 32 k-rows x 64B (swizzled), 4 slots
#define SBIAS    8192               // 256 floats
#define SQBUF    9216               // 4 x 32 floats
#define SCALE    9728               // 32 floats
#define SMEM_BYTES 9856

// ------------------------- device scratch ----------------------------
// W' fp16 pairs in exact A-fragment order (per 32-k chunk):
// idx = (((kc*2+ks)*16 + mb)*32 + lane)*4 + reg   (each u32 = 2 fp16, k-pair)
__device__ __align__(16) unsigned g_Wf[CC * CC / 2];
__device__ float g_bias[CC];

// ------------------------- helpers -----------------------------------
__device__ __forceinline__ uint32_t smem_u32(const void* p) {
    uint32_t a;
    asm("{ .reg .u64 t; cvta.to.shared.u64 t, %1; cvt.u32.u64 %0, t; }"
        : "=r"(a) : "l"(p));
    return a;
}
__device__ __forceinline__ uint32_t pkh2(float a, float b) {
    __half2 h = __floats2half2_rn(a, b);
    return *reinterpret_cast<uint32_t*>(&h);
}
__device__ __forceinline__ void ldsm_x2t(uint32_t* r, uint32_t addr) {
    asm volatile("ldmatrix.sync.aligned.m8n8.x2.trans.shared.b16 {%0,%1}, [%2];"
                 : "=r"(r[0]), "=r"(r[1]) : "r"(addr));
}
__device__ __forceinline__ void mma_f16(float* d, const uint32_t* a, const uint32_t* b) {
    asm volatile(
        "mma.sync.aligned.m16n8k16.row.col.f32.f16.f16.f32 "
        "{%0,%1,%2,%3}, {%4,%5,%6,%7}, {%8,%9}, {%0,%1,%2,%3};"
        : "+f"(d[0]), "+f"(d[1]), "+f"(d[2]), "+f"(d[3])
        : "r"(a[0]), "r"(a[1]), "r"(a[2]), "r"(a[3]), "r"(b[0]), "r"(b[1]));
}

// ------------------------- prep kernel -------------------------------
__global__ void fold_kernel(const float* __restrict__ W, const float* __restrict__ b,
                            const float* __restrict__ gamma, const float* __restrict__ beta,
                            const float* __restrict__ mean, const float* __restrict__ var) {
    int o = blockIdx.x;
    int j = threadIdx.x;          // c pair: c = 2j, 2j+1
    float inv = gamma[o] * rsqrtf(var[o] + 1e-5f);
    int c = 2 * j;
    float w0 = W[o * CC + c] * inv;
    float w1 = W[o * CC + c + 1] * inv;
    int kc = c >> 5;
    int ks = (c >> 4) & 1;
    int kl = c & 15;
    int mb = o >> 4;
    int lane = (o & 7) * 4 + ((kl >> 1) & 3);
    int reg  = ((o >> 3) & 1) + 2 * (kl >> 3);
    g_Wf[(((kc * 2 + ks) * 16 + mb) * 32 + lane) * 4 + reg] = pkh2(w0, w1);
    if (j == 0) g_bias[o] = b[o] * inv + beta[o] - mean[o] * inv;
}

// ------------------------- main kernel -------------------------------
// 128 threads, 4 warps (each owns 64 oc x full 32 pos). 3 CTAs/SM.
// Tile 256 oc x 32 pos; K in 8 chunks of 32.
// Deep pipelining: x LDG 4 chunks ahead / staged 3 ahead (4-ring);
// W frags (direct LDG, L1-hot) prefetched one full chunk ahead.
extern "C" __global__ void __launch_bounds__(128, 3)
caps_kernel(const float* __restrict__ x, float* __restrict__ out) {
    extern __shared__ char smem[];
    const uint32_t sbu = smem_u32(smem);
    const int t    = threadIdx.x;
    const int lane = t & 31;
    const int wm   = t >> 5;            // warp = m-slice
    const int m0   = wm * 64;
    const int bb   = blockIdx.y;
    const int l0   = blockIdx.x * TL;

    ((float*)(smem + SBIAS))[t]       = g_bias[t];
    ((float*)(smem + SBIAS))[t + 128] = g_bias[t + 128];

    const float* xg = x + (size_t)bb * CC * LL + l0;

    float acc[4][4][4];
    #pragma unroll
    for (int i = 0; i < 4; i++)
        #pragma unroll
        for (int j = 0; j < 4; j++)
            #pragma unroll
            for (int q = 0; q < 4; q++) acc[i][j][q] = 0.0f;

    // ---- x staging: thread t -> row r = t>>2 (k), seg p8 = t&3 (8 pos) --
    const int xr = t >> 2;
    const int p8 = t & 3;
    const uint32_t xsts = (uint32_t)(xr * 64 + ((p8 ^ ((xr >> 1) & 3)) << 4));
    float4 xva[2], xvb[2];              // two prefetch buffers
    auto ldg_x = [&](int kc, int buf) {
        const float* s = xg + (size_t)(kc * KC + xr) * LL + p8 * 8;
        xva[buf] = __ldg((const float4*)s);
        xvb[buf] = __ldg((const float4*)(s + 4));
    };
    auto stage_x = [&](int st, int buf) {
        uint4 u;
        u.x = pkh2(xva[buf].x, xva[buf].y); u.y = pkh2(xva[buf].z, xva[buf].w);
        u.z = pkh2(xvb[buf].x, xvb[buf].y); u.w = pkh2(xvb[buf].z, xvb[buf].w);
        *(uint4*)(smem + XOFF(st) + xsts) = u;
    };

    // ---- fragment loads ----------------------------------------------
    const uint4* Wg0 = (const uint4*)g_Wf;       // 512 uint4 per k16 step
    auto load_af = [&](uint32_t (*af)[4], int kc, int ks16) {
        const uint4* Wg = Wg0 + (size_t)(kc * 2 + ks16) * 512 + wm * 128 + lane;
        #pragma unroll
        for (int i = 0; i < 4; i++) {
            uint4 v = __ldg(Wg + i * 32);
            af[i][0] = v.x; af[i][1] = v.y; af[i][2] = v.z; af[i][3] = v.w;
        }
    };
    auto load_bf = [&](uint32_t (*bf)[2], int st, int ks16) {
        const uint32_t Xb = sbu + XOFF(st);
        int row = ks16 * 16 + (lane & 15);
        #pragma unroll
        for (int j = 0; j < 4; j++)
            ldsm_x2t(bf[j], Xb + (uint32_t)(row * 64
                               + ((j ^ ((row >> 1) & 3)) << 4)));
    };
    auto mma16 = [&](uint32_t (*af)[4], uint32_t (*bf)[2]) {
        #pragma unroll
        for (int i = 0; i < 4; i++)
            #pragma unroll
            for (int j = 0; j < 4; j++)
                mma_f16(acc[i][j], af[i], bf[j]);
    };

    // ---- prologue ------------------------------------------------------
    uint32_t af0[4][4], af1[4][4], bf0[4][2], bf1[4][2];
    ldg_x(0, 0); stage_x(0, 0);
    ldg_x(1, 0); stage_x(1, 0);
    ldg_x(2, 0); stage_x(2, 0);
    ldg_x(3, 1);                        // buf parity: chunk0 stages slot3 from buf1
    load_af(af0, 0, 0);
    load_af(af1, 0, 1);

    // ---- mainloop: 1 barrier/chunk, everything prefetched ---------------
    #pragma unroll
    for (int k = 0; k < NCHUNK; k++) {
        __syncthreads();                          // slot k%4 visible
        load_bf(bf0, k % NSTAGE, 0);
        load_bf(bf1, k % NSTAGE, 1);
        mma16(af0, bf0);
        if (k + 1 < NCHUNK) load_af(af0, k + 1, 0);      // next-chunk W (ks0)
        if (k + 3 < NCHUNK) stage_x((k + 3) % NSTAGE, (k & 1) ^ 1);
        if (k + 4 < NCHUNK) ldg_x(k + 4, k & 1);
        mma16(af1, bf1);
        if (k + 1 < NCHUNK) load_af(af1, k + 1, 1);      // next-chunk W (ks1)
    }

    // ---- epilogue: bias + squash + direct store --------------------------
    const float* sbias = (const float*)(smem + SBIAS);
    const int gid = lane >> 2;
    const int qid = lane & 3;

    float sqA[4], sqB[4];
    #pragma unroll
    for (int j = 0; j < 4; j++) { sqA[j] = 0.0f; sqB[j] = 0.0f; }

    #pragma unroll
    for (int i = 0; i < 4; i++) {
        int r0 = m0 + i * 16 + gid;
        float b0 = sbias[r0], b1 = sbias[r0 + 8];
        #pragma unroll
        for (int j = 0; j < 4; j++) {
            float y0 = acc[i][j][0] + b0;
            float y1 = acc[i][j][1] + b0;
            float y2 = acc[i][j][2] + b1;
            float y3 = acc[i][j][3] + b1;
            acc[i][j][0] = y0; acc[i][j][1] = y1;
            acc[i][j][2] = y2; acc[i][j][3] = y3;
            sqA[j] += y0 * y0 + y2 * y2;
            sqB[j] += y1 * y1 + y3 * y3;
        }
    }
    #pragma unroll
    for (int j = 0; j < 4; j++) {
        #pragma unroll
        for (int m = 4; m < 32; m <<= 1) {
            sqA[j] += __shfl_xor_sync(0xffffffffu, sqA[j], m);
            sqB[j] += __shfl_xor_sync(0xffffffffu, sqB[j], m);
        }
    }
    float* sqb = (float*)(smem + SQBUF);
    if (lane < 4) {
        #pragma unroll
        for (int j = 0; j < 4; j++) {
            int col = j * 8 + lane * 2;
            sqb[wm * 32 + col]     = sqA[j];
            sqb[wm * 32 + col + 1] = sqB[j];
        }
    }
    __syncthreads();
    if (t < 32) {
        float s = sqb[t] + sqb[32 + t] + sqb[64 + t] + sqb[96 + t];
        float n = sqrtf(s);
        ((float*)(smem + SCALE))[t] = s / ((1.0f + s) * (n + 1e-8f));
    }
    __syncthreads();

    const float* scl = (const float*)(smem + SCALE);
    float* og = out + ((size_t)bb * LL + l0) * CC;
    #pragma unroll
    for (int j = 0; j < 4; j++) {
        int c0 = j * 8 + qid * 2;            // position
        float s0 = scl[c0], s1 = scl[c0 + 1];
        float* p0 = og + (size_t)c0 * CC;
        float* p1 = og + (size_t)(c0 + 1) * CC;
        #pragma unroll
        for (int i = 0; i < 4; i++) {
            int r0 = m0 + i * 16 + gid;      // channel
            p0[r0]     = acc[i][j][0] * s0;
            p1[r0]     = acc[i][j][1] * s1;
            p0[r0 + 8] = acc[i][j][2] * s0;
            p1[r0 + 8] = acc[i][j][3] * s1;
        }
    }
}

// ------------------------- launch ------------------------------------
extern "C" void kernel_launch(void* const* d_in, const int* in_sizes, int n_in,
                              void* d_out, int out_size) {
    const float* x     = (const float*)d_in[0];
    const float* W     = (const float*)d_in[1];
    const float* b     = (const float*)d_in[2];
    const float* gamma = (const float*)d_in[3];
    const float* beta  = (const float*)d_in[4];
    const float* mean  = (const float*)d_in[5];
    const float* var   = (const float*)d_in[6];
    float* out = (float*)d_out;

    fold_kernel<<<CC, 128>>>(W, b, gamma, beta, mean, var);

    cudaFuncSetAttribute(caps_kernel,
                         cudaFuncAttributeMaxDynamicSharedMemorySize, SMEM_BYTES);
    dim3 grid(LL / TL, BB);
    caps_kernel<<<grid, 128, SMEM_BYTES>>>(x, out);
}